// round 11
// baseline (speedup 1.0000x reference)
#include <cuda_runtime.h>
#include <cuda_fp16.h>
#include <cstdint>

// ---------------------------------------------------------------------------
// packed helpers
// ---------------------------------------------------------------------------
__device__ __forceinline__ void unpack2(float& lo, float& hi,
                                        unsigned long long v) {
    asm("mov.b64 {%0, %1}, %2;" : "=f"(lo), "=f"(hi) : "l"(v));
}
__device__ __forceinline__ void ffma2(unsigned long long& d,
                                      unsigned long long a,
                                      unsigned long long b) {
    asm("fma.rn.f32x2 %0, %1, %2, %0;" : "+l"(d) : "l"(a), "l"(b));
}
__device__ __forceinline__ float tanh_fast(float x) {
    float y;
    asm("tanh.approx.f32 %0, %1;" : "=f"(y) : "f"(x));
    return y;
}
__device__ __forceinline__ unsigned tanh2_fast(unsigned x) {
    unsigned y;
    asm("tanh.approx.f16x2 %0, %1;" : "=r"(y) : "r"(x));
    return y;
}
__device__ __forceinline__ unsigned h22u(__half2 h) {
    return *reinterpret_cast<unsigned*>(&h);
}
__device__ __forceinline__ __half2 u2h2(unsigned u) {
    __half2 h;
    *reinterpret_cast<unsigned*>(&h) = u;
    return h;
}

// Shared pool (floats).
// SS path:  As(32*132) + Bsd(32*132 dup) = 8448.
// MLP path: ah(2176) + bh(1152) + Xt(2176) + Wo(1024) + swh(16) + c0 = 6545.
// TT path:  As(32*68)+Bs(32*68) = 4352.
#define POOL_FLOATS 8448

// ---------------------------------------------------------------------------
// Projection pass (256 threads): val[row,d] = 0.5*(X[row,:]@W[:,d]+b1d).
// Lane <-> row (X k-major in smem, conflict-free scalar reads); d-group is
// warp-uniform so W float4 reads are broadcast (1 wf). Each thread: 1 row x
// 8 d's. mode 0: dst half2 dup (v,v), stride 68. mode 1: dst half scalar,
// stride 72 halves (pairs packed naturally for the h2 mainloop).
// ---------------------------------------------------------------------------
__device__ __forceinline__ void proj_pass_h2(const float* __restrict__ src,
                                             const float* __restrict__ w,
                                             const float* __restrict__ b1,
                                             float* Xt, float* Wo, void* dstp,
                                             int mode, int tid) {
    for (int l = tid; l < 512; l += 256) {
        const int row = l >> 3;
        const int c = (l & 7) << 2;
        const float4 v = *(const float4*)(src + row * 32 + c);
        Xt[(c + 0) * 68 + row] = v.x;
        Xt[(c + 1) * 68 + row] = v.y;
        Xt[(c + 2) * 68 + row] = v.z;
        Xt[(c + 3) * 68 + row] = v.w;
    }
    for (int l = tid; l < 1024; l += 256) Wo[l] = w[l];  // [f][d] row-major
    __syncthreads();

    const int row = tid & 63;
    const int d0 = (tid >> 6) * 8;  // warp-uniform
    float acc[8];
#pragma unroll
    for (int q = 0; q < 8; q++) acc[q] = b1 ? b1[d0 + q] : 0.f;

#pragma unroll
    for (int f = 0; f < 32; f++) {
        const float x = Xt[f * 68 + row];
        const float4 w0 = *(const float4*)(Wo + f * 32 + d0);
        const float4 w1 = *(const float4*)(Wo + f * 32 + d0 + 4);
        acc[0] = fmaf(x, w0.x, acc[0]);
        acc[1] = fmaf(x, w0.y, acc[1]);
        acc[2] = fmaf(x, w0.z, acc[2]);
        acc[3] = fmaf(x, w0.w, acc[3]);
        acc[4] = fmaf(x, w1.x, acc[4]);
        acc[5] = fmaf(x, w1.y, acc[5]);
        acc[6] = fmaf(x, w1.z, acc[6]);
        acc[7] = fmaf(x, w1.w, acc[7]);
    }

    if (mode == 0) {
        __half2* dst = (__half2*)dstp;  // [32][68]
#pragma unroll
        for (int q = 0; q < 8; q++)
            dst[(d0 + q) * 68 + row] = __float2half2_rn(0.5f * acc[q]);
    } else {
        __half* dst = (__half*)dstp;  // [32][72]
#pragma unroll
        for (int q = 0; q < 8; q++)
            dst[(d0 + q) * 72 + row] = __float2half_rn(0.5f * acc[q]);
    }
    __syncthreads();
}

// ---------------------------------------------------------------------------
// Fused kernel, 256 threads, 4 CTAs/SM. 108 block-slots per batch:
//   r%3==0/1 -> SS half-tile (128x64, triangular ti<=tj, mirror direct).
//   r%3==2   -> m=r/3: m<16 ST (64x64, f16x2), m<32 TS, m==32 TT gram.
// ---------------------------------------------------------------------------
__global__ __launch_bounds__(256, 4) void adj_fused_kernel(
    const float* __restrict__ spatial, const float* __restrict__ temporal,
    const float* __restrict__ st_w1, const float* __restrict__ st_b1,
    const float* __restrict__ st_w2, const float* __restrict__ st_b2,
    const float* __restrict__ ts_w1, const float* __restrict__ ts_b1,
    const float* __restrict__ ts_w2, const float* __restrict__ ts_b2,
    float* __restrict__ out) {
    __shared__ __align__(16) float pool[POOL_FLOATS];

    const int b = blockIdx.x / 108;
    const int r = blockIdx.x % 108;
    const int tid = threadIdx.x;
    const int rm = r % 3;

    if (rm != 2) {
        // ====== SS gram: 128x64 half-tile, row-pair FFMA2, no packs ========
        const int s = r / 3;
        int ti = 0, rem = s;
#pragma unroll
        for (int t = 0; t < 8; t++) {
            if (rem >= 8 - ti) { rem -= 8 - ti; ti++; }
        }
        const int tj = ti + rem;
        const int cj = tj * 128 + rm * 64;

        float* As = pool;              // [32][132] k-major, 128 rows
        float* Bsd = pool + 32 * 132;  // [32][132] k-major, 64 cols DUP'd

        const float* Asrc = spatial + ((size_t)b * 1024 + ti * 128) * 32;
        const float* Bsrc = spatial + ((size_t)b * 1024 + cj) * 32;
        for (int l = tid; l < 1024; l += 256) {
            const int row = l >> 3;
            const int kq = (l & 7) << 2;
            const float4 va = *(const float4*)(Asrc + row * 32 + kq);
            As[(kq + 0) * 132 + row] = va.x;
            As[(kq + 1) * 132 + row] = va.y;
            As[(kq + 2) * 132 + row] = va.z;
            As[(kq + 3) * 132 + row] = va.w;
        }
        for (int l = tid; l < 512; l += 256) {
            const int c = l >> 3;
            const int kq = (l & 7) << 2;
            const float4 vb = *(const float4*)(Bsrc + c * 32 + kq);
            Bsd[(kq + 0) * 132 + 2 * c] = vb.x;
            Bsd[(kq + 0) * 132 + 2 * c + 1] = vb.x;
            Bsd[(kq + 1) * 132 + 2 * c] = vb.y;
            Bsd[(kq + 1) * 132 + 2 * c + 1] = vb.y;
            Bsd[(kq + 2) * 132 + 2 * c] = vb.z;
            Bsd[(kq + 2) * 132 + 2 * c + 1] = vb.z;
            Bsd[(kq + 3) * 132 + 2 * c] = vb.w;
            Bsd[(kq + 3) * 132 + 2 * c + 1] = vb.w;
        }
        __syncthreads();

        const int tx = tid & 15;  // cols tx*4..+3
        const int ty = tid >> 4;  // rows ty*8..+7
        unsigned long long acc[4][4];  // [row-pair][col]
#pragma unroll
        for (int ip = 0; ip < 4; ip++)
#pragma unroll
            for (int j = 0; j < 4; j++) acc[ip][j] = 0ull;

        // A rows ty*8: 2x LDS.128 = 4 ready row-pairs. B dup: 2x LDS.128 =
        // 4 ready (c,c) pairs. 4 loads + 16 FFMA2 per k, zero MOV packs.
        const ulonglong2* Aq = (const ulonglong2*)(As + ty * 8);
        const ulonglong2* Bq = (const ulonglong2*)(Bsd + tx * 8);
#pragma unroll
        for (int k = 0; k < 32; k++) {
            const ulonglong2 aA = Aq[k * 33];      // (r0,r1),(r2,r3)
            const ulonglong2 aB = Aq[k * 33 + 1];  // (r4,r5),(r6,r7)
            const ulonglong2 bA = Bq[k * 33];      // (c0,c0),(c1,c1)
            const ulonglong2 bB = Bq[k * 33 + 1];  // (c2,c2),(c3,c3)
            const unsigned long long ap[4] = {aA.x, aA.y, aB.x, aB.y};
            const unsigned long long bp[4] = {bA.x, bA.y, bB.x, bB.y};
#pragma unroll
            for (int ip = 0; ip < 4; ip++) {
                ffma2(acc[ip][0], ap[ip], bp[0]);
                ffma2(acc[ip][1], ap[ip], bp[1]);
                ffma2(acc[ip][2], ap[ip], bp[2]);
                ffma2(acc[ip][3], ap[ip], bp[3]);
            }
        }

        // Unpack row pairs -> v[8 rows][4 cols], activate.
        float v[8][4];
#pragma unroll
        for (int ip = 0; ip < 4; ip++)
#pragma unroll
            for (int j = 0; j < 4; j++)
                unpack2(v[2 * ip][j], v[2 * ip + 1][j], acc[ip][j]);
#pragma unroll
        for (int i = 0; i < 8; i++)
#pragma unroll
            for (int j = 0; j < 4; j++)
                v[i][j] = tanh_fast(fmaxf(v[i][j], 0.f));

        float* ob =
            out + ((size_t)b * 1088 + ti * 128 + ty * 8) * 1088 + cj + tx * 4;
#pragma unroll
        for (int i = 0; i < 8; i++) {
            float4 o = {v[i][0], v[i][1], v[i][2], v[i][3]};
            *(float4*)(ob + (size_t)i * 1088) = o;
        }

        if (ti == tj) return;

        float* om = out + ((size_t)b * 1088 + cj) * 1088 + ti * 128 + ty * 8;
#pragma unroll
        for (int j = 0; j < 4; j++) {
            const int col = tx * 4 + j;
            float4 lo = {v[0][j], v[1][j], v[2][j], v[3][j]};
            float4 hi = {v[4][j], v[5][j], v[6][j], v[7][j]};
            *(float4*)(om + (size_t)col * 1088) = lo;
            *(float4*)(om + (size_t)col * 1088 + 4) = hi;
        }
        return;
    }

    const int m = r / 3;
    if (m > 32) return;

    if (m == 32) {
        // ==================== TT gram: 64x64 f32 path ======================
        float* As = pool;  // [32][68]
        float* Bs = pool + 32 * 68;
        const float* Tsrc = temporal + (size_t)b * 64 * 32;
        for (int l = tid; l < 512; l += 256) {
            const int row = l >> 3;
            const int kq = (l & 7) << 2;
            const float4 v = *(const float4*)(Tsrc + row * 32 + kq);
            As[(kq + 0) * 68 + row] = v.x;
            As[(kq + 1) * 68 + row] = v.y;
            As[(kq + 2) * 68 + row] = v.z;
            As[(kq + 3) * 68 + row] = v.w;
            Bs[(kq + 0) * 68 + row] = v.x;
            Bs[(kq + 1) * 68 + row] = v.y;
            Bs[(kq + 2) * 68 + row] = v.z;
            Bs[(kq + 3) * 68 + row] = v.w;
        }
        __syncthreads();

        const int tx = tid & 15;
        const int ty = tid >> 4;
        float acc[4][4];
#pragma unroll
        for (int i = 0; i < 4; i++)
#pragma unroll
            for (int j = 0; j < 4; j++) acc[i][j] = 0.f;

        const float* ap = As + ty * 4;
        const float* bp = Bs + tx * 4;
#pragma unroll
        for (int k = 0; k < 32; k++) {
            const float4 a = *(const float4*)(ap + k * 68);
            const float4 bb = *(const float4*)(bp + k * 68);
            const float av[4] = {a.x, a.y, a.z, a.w};
            const float bv[4] = {bb.x, bb.y, bb.z, bb.w};
#pragma unroll
            for (int i = 0; i < 4; i++)
#pragma unroll
                for (int j = 0; j < 4; j++)
                    acc[i][j] = fmaf(av[i], bv[j], acc[i][j]);
        }

        float* ob =
            out + ((size_t)b * 1088 + 1024 + ty * 4) * 1088 + 1024 + tx * 4;
#pragma unroll
        for (int i = 0; i < 4; i++) {
            float4 v;
            v.x = tanh_fast(fmaxf(acc[i][0], 0.f));
            v.y = tanh_fast(fmaxf(acc[i][1], 0.f));
            v.z = tanh_fast(fmaxf(acc[i][2], 0.f));
            v.w = tanh_fast(fmaxf(acc[i][3], 0.f));
            *(float4*)(ob + (size_t)i * 1088) = v;
        }
        return;
    }

    // ==================== MLP (ST / TS): f16x2 path ========================
    __half2* ah = (__half2*)pool;            // [32][68] dup half2
    __half* bh = (__half*)(pool + 2176);     // [32][72] halves (=[32][36] h2)
    float* Xt = pool + 2176 + 1152;          // [32][68] k-major X
    float* Wo = pool + 2176 + 1152 + 2176;   // [32][32] w row-major
    __half2* swh = (__half2*)(pool + 2176 + 1152 + 2176 + 1024);  // [32]
    float* c0p = pool + 2176 + 1152 + 2176 + 1024 + 32;

    const bool isST = (m < 16);
    const float* w1 = isST ? st_w1 : ts_w1;
    const float* b1 = isST ? st_b1 : ts_b1;
    const float* w2 = isST ? st_w2 : ts_w2;
    const float* b2 = isST ? st_b2 : ts_b2;
    const float* asrc;
    const float* bsrc;
    int gi0, gj0;
    if (isST) {
        asrc = spatial + ((size_t)b * 1024 + m * 64) * 32;
        bsrc = temporal + (size_t)b * 64 * 32;
        gi0 = m * 64;
        gj0 = 1024;
    } else {
        asrc = temporal + (size_t)b * 64 * 32;
        bsrc = spatial + ((size_t)b * 1024 + (m - 16) * 64) * 32;
        gi0 = 1024;
        gj0 = (m - 16) * 64;
    }

    if (tid < 32) swh[tid] = __float2half2_rn(0.5f * w2[tid]);
    proj_pass_h2(asrc, w1, b1, Xt, Wo, ah, 0, tid);  // a' (sync covers swh)
    if (tid == 0) {
        float c = b2[0];
#pragma unroll
        for (int k = 0; k < 32; k++) c += 0.5f * w2[k];
        *c0p = c;
    }
    proj_pass_h2(bsrc, w1 + 1024, nullptr, Xt, Wo, bh, 1, tid);  // b'

    const int tx = tid & 15;  // col pairs tx*2, tx*2+1 -> cols tx*4..+3
    const int ty = tid >> 4;  // rows ty*4..+3
    __half2 acc2[4][2];
    const __half2 hz = __float2half2_rn(0.f);
#pragma unroll
    for (int i = 0; i < 4; i++) {
        acc2[i][0] = hz;
        acc2[i][1] = hz;
    }

    const __half2* ap = ah + ty * 4;
    const __half2* bp = (const __half2*)bh + tx * 2;
#pragma unroll
    for (int k = 0; k < 32; k++) {
        const uint2 aLo = *(const uint2*)(ap + k * 68);
        const uint2 aHi = *(const uint2*)(ap + k * 68 + 2);
        const uint2 bb = *(const uint2*)(bp + k * 36);
        const __half2 w2k = swh[k];
        const unsigned au[4] = {aLo.x, aLo.y, aHi.x, aHi.y};
#pragma unroll
        for (int i = 0; i < 4; i++) {
            const __half2 ai = u2h2(au[i]);
            const __half2 t0 = u2h2(tanh2_fast(h22u(__hadd2(ai, u2h2(bb.x)))));
            const __half2 t1 = u2h2(tanh2_fast(h22u(__hadd2(ai, u2h2(bb.y)))));
            acc2[i][0] = __hfma2(t0, w2k, acc2[i][0]);
            acc2[i][1] = __hfma2(t1, w2k, acc2[i][1]);
        }
    }

    const float c0 = *c0p;
    float* ob = out + ((size_t)b * 1088 + gi0 + ty * 4) * 1088 + gj0 + tx * 4;
#pragma unroll
    for (int i = 0; i < 4; i++) {
        const float2 f0 = __half22float2(acc2[i][0]);
        const float2 f1 = __half22float2(acc2[i][1]);
        float4 v;
        v.x = tanh_fast(fmaxf(f0.x + c0, 0.f));
        v.y = tanh_fast(fmaxf(f0.y + c0, 0.f));
        v.z = tanh_fast(fmaxf(f1.x + c0, 0.f));
        v.w = tanh_fast(fmaxf(f1.y + c0, 0.f));
        *(float4*)(ob + (size_t)i * 1088) = v;
    }
}

extern "C" void kernel_launch(void* const* d_in, const int* in_sizes, int n_in,
                              void* d_out, int out_size) {
    const float* spatial = (const float*)d_in[0];   // [32,1024,32]
    const float* temporal = (const float*)d_in[1];  // [32,64,32]
    const float* st_w1 = (const float*)d_in[2];     // [64,32]
    const float* st_b1 = (const float*)d_in[3];     // [32]
    const float* st_w2 = (const float*)d_in[4];     // [32,1]
    const float* st_b2 = (const float*)d_in[5];     // [1]
    const float* ts_w1 = (const float*)d_in[6];
    const float* ts_b1 = (const float*)d_in[7];
    const float* ts_w2 = (const float*)d_in[8];
    const float* ts_b2 = (const float*)d_in[9];
    float* out = (float*)d_out;                     // [32,1088,1088]

    adj_fused_kernel<<<32 * 108, 256>>>(spatial, temporal, st_w1, st_b1, st_w2,
                                        st_b2, ts_w1, ts_b1, ts_w2, ts_b2, out);
}

// round 13
// speedup vs baseline: 1.1940x; 1.1940x over previous
#include <cuda_runtime.h>
#include <cuda_fp16.h>
#include <cstdint>

// ---------------------------------------------------------------------------
// packed helpers
// ---------------------------------------------------------------------------
__device__ __forceinline__ unsigned long long pack2(float lo, float hi) {
    unsigned long long r;
    asm("mov.b64 %0, {%1, %2};" : "=l"(r) : "f"(lo), "f"(hi));
    return r;
}
__device__ __forceinline__ void unpack2(float& lo, float& hi,
                                        unsigned long long v) {
    asm("mov.b64 {%0, %1}, %2;" : "=f"(lo), "=f"(hi) : "l"(v));
}
__device__ __forceinline__ void ffma2(unsigned long long& d,
                                      unsigned long long a,
                                      unsigned long long b) {
    asm("fma.rn.f32x2 %0, %1, %2, %0;" : "+l"(d) : "l"(a), "l"(b));
}
__device__ __forceinline__ float tanh_fast(float x) {
    float y;
    asm("tanh.approx.f32 %0, %1;" : "=f"(y) : "f"(x));
    return y;
}
__device__ __forceinline__ unsigned tanh2_fast(unsigned x) {
    unsigned y;
    asm("tanh.approx.f16x2 %0, %1;" : "=r"(y) : "r"(x));
    return y;
}
__device__ __forceinline__ unsigned h22u(__half2 h) {
    return *reinterpret_cast<unsigned*>(&h);
}
__device__ __forceinline__ __half2 u2h2(unsigned u) {
    __half2 h;
    *reinterpret_cast<unsigned*>(&h) = u;
    return h;
}

// Shared pool (floats).
// SS path:  As(32*132) + Bs(32*68) = 6400.
// MLP path: ah(2176) + bh(1152) + Xt(2176) + Wo(1024) + swh(16) + c0 = 6545.
// TT path:  As(32*68)+Bs(32*68) = 4352.
#define POOL_FLOATS 8448

// ---------------------------------------------------------------------------
// Projection pass (256 threads): val[row,d] = 0.5*(X[row,:]@W[:,d]+b1d).
// Lane <-> row (X k-major in smem, conflict-free scalar reads); d-group is
// warp-uniform so W float4 reads are broadcast (1 wf each). Each thread:
// 1 row x 8 d's. mode 0: dst half2 dup (v,v), stride 68. mode 1: dst half
// scalar, stride 72 halves (pairs packed naturally for the h2 mainloop).
// ---------------------------------------------------------------------------
__device__ __forceinline__ void proj_pass_h2(const float* __restrict__ src,
                                             const float* __restrict__ w,
                                             const float* __restrict__ b1,
                                             float* Xt, float* Wo, void* dstp,
                                             int mode, int tid) {
    for (int l = tid; l < 512; l += 256) {
        const int row = l >> 3;
        const int c = (l & 7) << 2;
        const float4 v = *(const float4*)(src + row * 32 + c);
        Xt[(c + 0) * 68 + row] = v.x;
        Xt[(c + 1) * 68 + row] = v.y;
        Xt[(c + 2) * 68 + row] = v.z;
        Xt[(c + 3) * 68 + row] = v.w;
    }
    for (int l = tid; l < 1024; l += 256) Wo[l] = w[l];  // [f][d] row-major
    __syncthreads();

    const int row = tid & 63;
    const int d0 = (tid >> 6) * 8;  // warp-uniform
    float acc[8];
#pragma unroll
    for (int q = 0; q < 8; q++) acc[q] = b1 ? b1[d0 + q] : 0.f;

#pragma unroll
    for (int f = 0; f < 32; f++) {
        const float x = Xt[f * 68 + row];
        const float4 w0 = *(const float4*)(Wo + f * 32 + d0);
        const float4 w1 = *(const float4*)(Wo + f * 32 + d0 + 4);
        acc[0] = fmaf(x, w0.x, acc[0]);
        acc[1] = fmaf(x, w0.y, acc[1]);
        acc[2] = fmaf(x, w0.z, acc[2]);
        acc[3] = fmaf(x, w0.w, acc[3]);
        acc[4] = fmaf(x, w1.x, acc[4]);
        acc[5] = fmaf(x, w1.y, acc[5]);
        acc[6] = fmaf(x, w1.z, acc[6]);
        acc[7] = fmaf(x, w1.w, acc[7]);
    }

    if (mode == 0) {
        __half2* dst = (__half2*)dstp;  // [32][68]
#pragma unroll
        for (int q = 0; q < 8; q++)
            dst[(d0 + q) * 68 + row] = __float2half2_rn(0.5f * acc[q]);
    } else {
        __half* dst = (__half*)dstp;  // [32][72]
#pragma unroll
        for (int q = 0; q < 8; q++)
            dst[(d0 + q) * 72 + row] = __float2half_rn(0.5f * acc[q]);
    }
    __syncthreads();
}

// ---------------------------------------------------------------------------
// Fused kernel, 256 threads, 4 CTAs/SM. 108 block-slots per batch:
//   r%3==0/1 -> SS half-tile (128x64, triangular ti<=tj, mirror direct).
//   r%3==2   -> m=r/3: m<16 ST (64x64, f16x2), m<32 TS, m==32 TT gram.
// SS/TT/MLP mainloops are the proven R10 forms; only proj is the new layout.
// ---------------------------------------------------------------------------
__global__ __launch_bounds__(256, 4) void adj_fused_kernel(
    const float* __restrict__ spatial, const float* __restrict__ temporal,
    const float* __restrict__ st_w1, const float* __restrict__ st_b1,
    const float* __restrict__ st_w2, const float* __restrict__ st_b2,
    const float* __restrict__ ts_w1, const float* __restrict__ ts_b1,
    const float* __restrict__ ts_w2, const float* __restrict__ ts_b2,
    float* __restrict__ out) {
    __shared__ __align__(16) float pool[POOL_FLOATS];

    const int b = blockIdx.x / 108;
    const int r = blockIdx.x % 108;
    const int tid = threadIdx.x;
    const int rm = r % 3;

    if (rm != 2) {
        // ====== SS gram: 128x64 half-tile, 8x4 per thread, FFMA2 ===========
        const int s = r / 3;
        int ti = 0, rem = s;
#pragma unroll
        for (int t = 0; t < 8; t++) {
            if (rem >= 8 - ti) { rem -= 8 - ti; ti++; }
        }
        const int tj = ti + rem;
        const int cj = tj * 128 + rm * 64;

        float* As = pool;             // [32][132] k-major, 128 rows
        float* Bs = pool + 32 * 132;  // [32][68]  k-major, 64 cols

        const float* Asrc = spatial + ((size_t)b * 1024 + ti * 128) * 32;
        const float* Bsrc = spatial + ((size_t)b * 1024 + cj) * 32;
        for (int l = tid; l < 1024; l += 256) {
            const int row = l >> 3;
            const int kq = (l & 7) << 2;
            const float4 va = *(const float4*)(Asrc + row * 32 + kq);
            As[(kq + 0) * 132 + row] = va.x;
            As[(kq + 1) * 132 + row] = va.y;
            As[(kq + 2) * 132 + row] = va.z;
            As[(kq + 3) * 132 + row] = va.w;
        }
        for (int l = tid; l < 512; l += 256) {
            const int row = l >> 3;
            const int kq = (l & 7) << 2;
            const float4 vb = *(const float4*)(Bsrc + row * 32 + kq);
            Bs[(kq + 0) * 68 + row] = vb.x;
            Bs[(kq + 1) * 68 + row] = vb.y;
            Bs[(kq + 2) * 68 + row] = vb.z;
            Bs[(kq + 3) * 68 + row] = vb.w;
        }
        __syncthreads();

        const int tx = tid & 15;
        const int ty = tid >> 4;
        unsigned long long acc[8][2];
#pragma unroll
        for (int i = 0; i < 8; i++) {
            acc[i][0] = 0ull;
            acc[i][1] = 0ull;
        }

        const float* Ap = As + ty * 8;
        const unsigned long long* Bq = (const unsigned long long*)(Bs + tx * 4);
#pragma unroll
        for (int k = 0; k < 32; k++) {
            const float4 a0 = *(const float4*)(Ap + k * 132);
            const float4 a1 = *(const float4*)(Ap + k * 132 + 4);
            const unsigned long long bp0 = Bq[k * 34];
            const unsigned long long bp1 = Bq[k * 34 + 1];
            const float av[8] = {a0.x, a0.y, a0.z, a0.w,
                                 a1.x, a1.y, a1.z, a1.w};
#pragma unroll
            for (int i = 0; i < 8; i++) {
                const unsigned long long ad = pack2(av[i], av[i]);
                ffma2(acc[i][0], ad, bp0);
                ffma2(acc[i][1], ad, bp1);
            }
        }

        float v[8][4];
#pragma unroll
        for (int i = 0; i < 8; i++) {
            unpack2(v[i][0], v[i][1], acc[i][0]);
            unpack2(v[i][2], v[i][3], acc[i][1]);
#pragma unroll
            for (int j = 0; j < 4; j++)
                v[i][j] = tanh_fast(fmaxf(v[i][j], 0.f));
        }

        float* ob =
            out + ((size_t)b * 1088 + ti * 128 + ty * 8) * 1088 + cj + tx * 4;
#pragma unroll
        for (int i = 0; i < 8; i++) {
            float4 o = {v[i][0], v[i][1], v[i][2], v[i][3]};
            *(float4*)(ob + (size_t)i * 1088) = o;
        }

        if (ti == tj) return;

        float* om = out + ((size_t)b * 1088 + cj) * 1088 + ti * 128 + ty * 8;
#pragma unroll
        for (int j = 0; j < 4; j++) {
            const int col = tx * 4 + j;
            float4 lo = {v[0][j], v[1][j], v[2][j], v[3][j]};
            float4 hi = {v[4][j], v[5][j], v[6][j], v[7][j]};
            *(float4*)(om + (size_t)col * 1088) = lo;
            *(float4*)(om + (size_t)col * 1088 + 4) = hi;
        }
        return;
    }

    const int m = r / 3;
    if (m > 32) return;

    if (m == 32) {
        // ==================== TT gram: 64x64 f32 path ======================
        float* As = pool;  // [32][68]
        float* Bs = pool + 32 * 68;
        const float* Tsrc = temporal + (size_t)b * 64 * 32;
        for (int l = tid; l < 512; l += 256) {
            const int row = l >> 3;
            const int kq = (l & 7) << 2;
            const float4 v = *(const float4*)(Tsrc + row * 32 + kq);
            As[(kq + 0) * 68 + row] = v.x;
            As[(kq + 1) * 68 + row] = v.y;
            As[(kq + 2) * 68 + row] = v.z;
            As[(kq + 3) * 68 + row] = v.w;
            Bs[(kq + 0) * 68 + row] = v.x;
            Bs[(kq + 1) * 68 + row] = v.y;
            Bs[(kq + 2) * 68 + row] = v.z;
            Bs[(kq + 3) * 68 + row] = v.w;
        }
        __syncthreads();

        const int tx = tid & 15;
        const int ty = tid >> 4;
        float acc[4][4];
#pragma unroll
        for (int i = 0; i < 4; i++)
#pragma unroll
            for (int j = 0; j < 4; j++) acc[i][j] = 0.f;

        const float* ap = As + ty * 4;
        const float* bp = Bs + tx * 4;
#pragma unroll
        for (int k = 0; k < 32; k++) {
            const float4 a = *(const float4*)(ap + k * 68);
            const float4 bb = *(const float4*)(bp + k * 68);
            const float av[4] = {a.x, a.y, a.z, a.w};
            const float bv[4] = {bb.x, bb.y, bb.z, bb.w};
#pragma unroll
            for (int i = 0; i < 4; i++)
#pragma unroll
                for (int j = 0; j < 4; j++)
                    acc[i][j] = fmaf(av[i], bv[j], acc[i][j]);
        }

        float* ob =
            out + ((size_t)b * 1088 + 1024 + ty * 4) * 1088 + 1024 + tx * 4;
#pragma unroll
        for (int i = 0; i < 4; i++) {
            float4 v;
            v.x = tanh_fast(fmaxf(acc[i][0], 0.f));
            v.y = tanh_fast(fmaxf(acc[i][1], 0.f));
            v.z = tanh_fast(fmaxf(acc[i][2], 0.f));
            v.w = tanh_fast(fmaxf(acc[i][3], 0.f));
            *(float4*)(ob + (size_t)i * 1088) = v;
        }
        return;
    }

    // ==================== MLP (ST / TS): f16x2 path ========================
    __half2* ah = (__half2*)pool;           // [32][68] dup half2
    __half* bh = (__half*)(pool + 2176);    // [32][72] halves (=[32][36] h2)
    float* Xt = pool + 2176 + 1152;         // [32][68] k-major X
    float* Wo = pool + 2176 + 1152 + 2176;  // [32][32] w row-major
    __half2* swh = (__half2*)(pool + 2176 + 1152 + 2176 + 1024);  // [32]
    float* c0p = pool + 2176 + 1152 + 2176 + 1024 + 32;

    const bool isST = (m < 16);
    const float* w1 = isST ? st_w1 : ts_w1;
    const float* b1 = isST ? st_b1 : ts_b1;
    const float* w2 = isST ? st_w2 : ts_w2;
    const float* b2 = isST ? st_b2 : ts_b2;
    const float* asrc;
    const float* bsrc;
    int gi0, gj0;
    if (isST) {
        asrc = spatial + ((size_t)b * 1024 + m * 64) * 32;
        bsrc = temporal + (size_t)b * 64 * 32;
        gi0 = m * 64;
        gj0 = 1024;
    } else {
        asrc = temporal + (size_t)b * 64 * 32;
        bsrc = spatial + ((size_t)b * 1024 + (m - 16) * 64) * 32;
        gi0 = 1024;
        gj0 = (m - 16) * 64;
    }

    if (tid < 32) swh[tid] = __float2half2_rn(0.5f * w2[tid]);
    proj_pass_h2(asrc, w1, b1, Xt, Wo, ah, 0, tid);  // a' (sync covers swh)
    if (tid == 0) {
        float c = b2[0];
#pragma unroll
        for (int k = 0; k < 32; k++) c += 0.5f * w2[k];
        *c0p = c;
    }
    proj_pass_h2(bsrc, w1 + 1024, nullptr, Xt, Wo, bh, 1, tid);  // b'

    const int tx = tid & 15;  // col pairs tx*2, tx*2+1 -> cols tx*4..+3
    const int ty = tid >> 4;  // rows ty*4..+3
    __half2 acc2[4][2];
    const __half2 hz = __float2half2_rn(0.f);
#pragma unroll
    for (int i = 0; i < 4; i++) {
        acc2[i][0] = hz;
        acc2[i][1] = hz;
    }

    const __half2* ap = ah + ty * 4;
    const __half2* bp = (const __half2*)bh + tx * 2;
#pragma unroll
    for (int k = 0; k < 32; k++) {
        const uint2 aLo = *(const uint2*)(ap + k * 68);
        const uint2 aHi = *(const uint2*)(ap + k * 68 + 2);
        const uint2 bb = *(const uint2*)(bp + k * 36);
        const __half2 w2k = swh[k];
        const unsigned au[4] = {aLo.x, aLo.y, aHi.x, aHi.y};
#pragma unroll
        for (int i = 0; i < 4; i++) {
            const __half2 ai = u2h2(au[i]);
            const __half2 t0 = u2h2(tanh2_fast(h22u(__hadd2(ai, u2h2(bb.x)))));
            const __half2 t1 = u2h2(tanh2_fast(h22u(__hadd2(ai, u2h2(bb.y)))));
            acc2[i][0] = __hfma2(t0, w2k, acc2[i][0]);
            acc2[i][1] = __hfma2(t1, w2k, acc2[i][1]);
        }
    }

    const float c0 = *c0p;
    float* ob = out + ((size_t)b * 1088 + gi0 + ty * 4) * 1088 + gj0 + tx * 4;
#pragma unroll
    for (int i = 0; i < 4; i++) {
        const float2 f0 = __half22float2(acc2[i][0]);
        const float2 f1 = __half22float2(acc2[i][1]);
        float4 v;
        v.x = tanh_fast(fmaxf(f0.x + c0, 0.f));
        v.y = tanh_fast(fmaxf(f0.y + c0, 0.f));
        v.z = tanh_fast(fmaxf(f1.x + c0, 0.f));
        v.w = tanh_fast(fmaxf(f1.y + c0, 0.f));
        *(float4*)(ob + (size_t)i * 1088) = v;
    }
}

extern "C" void kernel_launch(void* const* d_in, const int* in_sizes, int n_in,
                              void* d_out, int out_size) {
    const float* spatial = (const float*)d_in[0];   // [32,1024,32]
    const float* temporal = (const float*)d_in[1];  // [32,64,32]
    const float* st_w1 = (const float*)d_in[2];     // [64,32]
    const float* st_b1 = (const float*)d_in[3];     // [32]
    const float* st_w2 = (const float*)d_in[4];     // [32,1]
    const float* st_b2 = (const float*)d_in[5];     // [1]
    const float* ts_w1 = (const float*)d_in[6];
    const float* ts_b1 = (const float*)d_in[7];
    const float* ts_w2 = (const float*)d_in[8];
    const float* ts_b2 = (const float*)d_in[9];
    float* out = (float*)d_out;                     // [32,1088,1088]

    adj_fused_kernel<<<32 * 108, 256>>>(spatial, temporal, st_w1, st_b1, st_w2,
                                        st_b2, ts_w1, ts_b1, ts_w2, ts_b2, out);
}

// round 14
// speedup vs baseline: 1.1958x; 1.0015x over previous
#include <cuda_runtime.h>
#include <cuda_fp16.h>
#include <cstdint>

// ---------------------------------------------------------------------------
// packed helpers
// ---------------------------------------------------------------------------
__device__ __forceinline__ unsigned long long pack2(float lo, float hi) {
    unsigned long long r;
    asm("mov.b64 %0, {%1, %2};" : "=l"(r) : "f"(lo), "f"(hi));
    return r;
}
__device__ __forceinline__ void unpack2(float& lo, float& hi,
                                        unsigned long long v) {
    asm("mov.b64 {%0, %1}, %2;" : "=f"(lo), "=f"(hi) : "l"(v));
}
__device__ __forceinline__ void ffma2(unsigned long long& d,
                                      unsigned long long a,
                                      unsigned long long b) {
    asm("fma.rn.f32x2 %0, %1, %2, %0;" : "+l"(d) : "l"(a), "l"(b));
}
__device__ __forceinline__ float tanh_fast(float x) {
    float y;
    asm("tanh.approx.f32 %0, %1;" : "=f"(y) : "f"(x));
    return y;
}
__device__ __forceinline__ unsigned tanh2_fast(unsigned x) {
    unsigned y;
    asm("tanh.approx.f16x2 %0, %1;" : "=r"(y) : "r"(x));
    return y;
}
__device__ __forceinline__ unsigned h22u(__half2 h) {
    return *reinterpret_cast<unsigned*>(&h);
}
__device__ __forceinline__ __half2 u2h2(unsigned u) {
    __half2 h;
    *reinterpret_cast<unsigned*>(&h) = u;
    return h;
}

// Shared pool (floats).
// SS path:  As(32*132) + Bs(32*68) = 6400.
// MLP path: ah(2176) + bh(1152) + Xt(2176) + Wo(1024) + swh(16) + c0 = 6545.
// TT path:  As(32*68)+Bs(32*68) = 4352.
#define POOL_FLOATS 8448

// ---------------------------------------------------------------------------
// Projection pass (256 threads): val[row,d] = 0.5*(X[row,:]@W[:,d]+b1d).
// Lane <-> row (X k-major in smem, conflict-free scalar reads); d-group is
// warp-uniform so W float4 reads are broadcast (1 wf each). Each thread:
// 1 row x 8 d's. mode 0: dst half2 dup (v,v), stride 68. mode 1: dst half
// scalar, stride 72 halves (pairs packed naturally for the h2 mainloop).
// ---------------------------------------------------------------------------
__device__ __forceinline__ void proj_pass_h2(const float* __restrict__ src,
                                             const float* __restrict__ w,
                                             const float* __restrict__ b1,
                                             float* Xt, float* Wo, void* dstp,
                                             int mode, int tid) {
    for (int l = tid; l < 512; l += 256) {
        const int row = l >> 3;
        const int c = (l & 7) << 2;
        const float4 v = *(const float4*)(src + row * 32 + c);
        Xt[(c + 0) * 68 + row] = v.x;
        Xt[(c + 1) * 68 + row] = v.y;
        Xt[(c + 2) * 68 + row] = v.z;
        Xt[(c + 3) * 68 + row] = v.w;
    }
    for (int l = tid; l < 1024; l += 256) Wo[l] = w[l];  // [f][d] row-major
    __syncthreads();

    const int row = tid & 63;
    const int d0 = (tid >> 6) * 8;  // warp-uniform
    float acc[8];
#pragma unroll
    for (int q = 0; q < 8; q++) acc[q] = b1 ? b1[d0 + q] : 0.f;

#pragma unroll
    for (int f = 0; f < 32; f++) {
        const float x = Xt[f * 68 + row];
        const float4 w0 = *(const float4*)(Wo + f * 32 + d0);
        const float4 w1 = *(const float4*)(Wo + f * 32 + d0 + 4);
        acc[0] = fmaf(x, w0.x, acc[0]);
        acc[1] = fmaf(x, w0.y, acc[1]);
        acc[2] = fmaf(x, w0.z, acc[2]);
        acc[3] = fmaf(x, w0.w, acc[3]);
        acc[4] = fmaf(x, w1.x, acc[4]);
        acc[5] = fmaf(x, w1.y, acc[5]);
        acc[6] = fmaf(x, w1.z, acc[6]);
        acc[7] = fmaf(x, w1.w, acc[7]);
    }

    if (mode == 0) {
        __half2* dst = (__half2*)dstp;  // [32][68]
#pragma unroll
        for (int q = 0; q < 8; q++)
            dst[(d0 + q) * 68 + row] = __float2half2_rn(0.5f * acc[q]);
    } else {
        __half* dst = (__half*)dstp;  // [32][72]
#pragma unroll
        for (int q = 0; q < 8; q++)
            dst[(d0 + q) * 72 + row] = __float2half_rn(0.5f * acc[q]);
    }
    __syncthreads();
}

// ---------------------------------------------------------------------------
// Fused kernel, 256 threads, 4 CTAs/SM. 108 block-slots per batch:
//   r%3==0/1 -> SS half-tile (128x64, triangular ti<=tj, mirror direct).
//   r%3==2   -> m=r/3: m<16 ST (64x64, f16x2), m<32 TS, m==32 TT gram.
// SS/TT/MLP mainloops are the proven R10 forms; only proj is the new layout.
// ---------------------------------------------------------------------------
__global__ __launch_bounds__(256, 4) void adj_fused_kernel(
    const float* __restrict__ spatial, const float* __restrict__ temporal,
    const float* __restrict__ st_w1, const float* __restrict__ st_b1,
    const float* __restrict__ st_w2, const float* __restrict__ st_b2,
    const float* __restrict__ ts_w1, const float* __restrict__ ts_b1,
    const float* __restrict__ ts_w2, const float* __restrict__ ts_b2,
    float* __restrict__ out) {
    __shared__ __align__(16) float pool[POOL_FLOATS];

    const int b = blockIdx.x / 108;
    const int r = blockIdx.x % 108;
    const int tid = threadIdx.x;
    const int rm = r % 3;

    if (rm != 2) {
        // ====== SS gram: 128x64 half-tile, 8x4 per thread, FFMA2 ===========
        const int s = r / 3;
        int ti = 0, rem = s;
#pragma unroll
        for (int t = 0; t < 8; t++) {
            if (rem >= 8 - ti) { rem -= 8 - ti; ti++; }
        }
        const int tj = ti + rem;
        const int cj = tj * 128 + rm * 64;

        float* As = pool;             // [32][132] k-major, 128 rows
        float* Bs = pool + 32 * 132;  // [32][68]  k-major, 64 cols

        const float* Asrc = spatial + ((size_t)b * 1024 + ti * 128) * 32;
        const float* Bsrc = spatial + ((size_t)b * 1024 + cj) * 32;
        for (int l = tid; l < 1024; l += 256) {
            const int row = l >> 3;
            const int kq = (l & 7) << 2;
            const float4 va = *(const float4*)(Asrc + row * 32 + kq);
            As[(kq + 0) * 132 + row] = va.x;
            As[(kq + 1) * 132 + row] = va.y;
            As[(kq + 2) * 132 + row] = va.z;
            As[(kq + 3) * 132 + row] = va.w;
        }
        for (int l = tid; l < 512; l += 256) {
            const int row = l >> 3;
            const int kq = (l & 7) << 2;
            const float4 vb = *(const float4*)(Bsrc + row * 32 + kq);
            Bs[(kq + 0) * 68 + row] = vb.x;
            Bs[(kq + 1) * 68 + row] = vb.y;
            Bs[(kq + 2) * 68 + row] = vb.z;
            Bs[(kq + 3) * 68 + row] = vb.w;
        }
        __syncthreads();

        const int tx = tid & 15;
        const int ty = tid >> 4;
        unsigned long long acc[8][2];
#pragma unroll
        for (int i = 0; i < 8; i++) {
            acc[i][0] = 0ull;
            acc[i][1] = 0ull;
        }

        const float* Ap = As + ty * 8;
        const unsigned long long* Bq = (const unsigned long long*)(Bs + tx * 4);
#pragma unroll
        for (int k = 0; k < 32; k++) {
            const float4 a0 = *(const float4*)(Ap + k * 132);
            const float4 a1 = *(const float4*)(Ap + k * 132 + 4);
            const unsigned long long bp0 = Bq[k * 34];
            const unsigned long long bp1 = Bq[k * 34 + 1];
            const float av[8] = {a0.x, a0.y, a0.z, a0.w,
                                 a1.x, a1.y, a1.z, a1.w};
#pragma unroll
            for (int i = 0; i < 8; i++) {
                const unsigned long long ad = pack2(av[i], av[i]);
                ffma2(acc[i][0], ad, bp0);
                ffma2(acc[i][1], ad, bp1);
            }
        }

        float v[8][4];
#pragma unroll
        for (int i = 0; i < 8; i++) {
            unpack2(v[i][0], v[i][1], acc[i][0]);
            unpack2(v[i][2], v[i][3], acc[i][1]);
#pragma unroll
            for (int j = 0; j < 4; j++)
                v[i][j] = tanh_fast(fmaxf(v[i][j], 0.f));
        }

        float* ob =
            out + ((size_t)b * 1088 + ti * 128 + ty * 8) * 1088 + cj + tx * 4;
#pragma unroll
        for (int i = 0; i < 8; i++) {
            float4 o = {v[i][0], v[i][1], v[i][2], v[i][3]};
            *(float4*)(ob + (size_t)i * 1088) = o;
        }

        if (ti == tj) return;

        float* om = out + ((size_t)b * 1088 + cj) * 1088 + ti * 128 + ty * 8;
#pragma unroll
        for (int j = 0; j < 4; j++) {
            const int col = tx * 4 + j;
            float4 lo = {v[0][j], v[1][j], v[2][j], v[3][j]};
            float4 hi = {v[4][j], v[5][j], v[6][j], v[7][j]};
            *(float4*)(om + (size_t)col * 1088) = lo;
            *(float4*)(om + (size_t)col * 1088 + 4) = hi;
        }
        return;
    }

    const int m = r / 3;
    if (m > 32) return;

    if (m == 32) {
        // ==================== TT gram: 64x64 f32 path ======================
        float* As = pool;  // [32][68]
        float* Bs = pool + 32 * 68;
        const float* Tsrc = temporal + (size_t)b * 64 * 32;
        for (int l = tid; l < 512; l += 256) {
            const int row = l >> 3;
            const int kq = (l & 7) << 2;
            const float4 v = *(const float4*)(Tsrc + row * 32 + kq);
            As[(kq + 0) * 68 + row] = v.x;
            As[(kq + 1) * 68 + row] = v.y;
            As[(kq + 2) * 68 + row] = v.z;
            As[(kq + 3) * 68 + row] = v.w;
            Bs[(kq + 0) * 68 + row] = v.x;
            Bs[(kq + 1) * 68 + row] = v.y;
            Bs[(kq + 2) * 68 + row] = v.z;
            Bs[(kq + 3) * 68 + row] = v.w;
        }
        __syncthreads();

        const int tx = tid & 15;
        const int ty = tid >> 4;
        float acc[4][4];
#pragma unroll
        for (int i = 0; i < 4; i++)
#pragma unroll
            for (int j = 0; j < 4; j++) acc[i][j] = 0.f;

        const float* ap = As + ty * 4;
        const float* bp = Bs + tx * 4;
#pragma unroll
        for (int k = 0; k < 32; k++) {
            const float4 a = *(const float4*)(ap + k * 68);
            const float4 bb = *(const float4*)(bp + k * 68);
            const float av[4] = {a.x, a.y, a.z, a.w};
            const float bv[4] = {bb.x, bb.y, bb.z, bb.w};
#pragma unroll
            for (int i = 0; i < 4; i++)
#pragma unroll
                for (int j = 0; j < 4; j++)
                    acc[i][j] = fmaf(av[i], bv[j], acc[i][j]);
        }

        float* ob =
            out + ((size_t)b * 1088 + 1024 + ty * 4) * 1088 + 1024 + tx * 4;
#pragma unroll
        for (int i = 0; i < 4; i++) {
            float4 v;
            v.x = tanh_fast(fmaxf(acc[i][0], 0.f));
            v.y = tanh_fast(fmaxf(acc[i][1], 0.f));
            v.z = tanh_fast(fmaxf(acc[i][2], 0.f));
            v.w = tanh_fast(fmaxf(acc[i][3], 0.f));
            *(float4*)(ob + (size_t)i * 1088) = v;
        }
        return;
    }

    // ==================== MLP (ST / TS): f16x2 path ========================
    __half2* ah = (__half2*)pool;           // [32][68] dup half2
    __half* bh = (__half*)(pool + 2176);    // [32][72] halves (=[32][36] h2)
    float* Xt = pool + 2176 + 1152;         // [32][68] k-major X
    float* Wo = pool + 2176 + 1152 + 2176;  // [32][32] w row-major
    __half2* swh = (__half2*)(pool + 2176 + 1152 + 2176 + 1024);  // [32]
    float* c0p = pool + 2176 + 1152 + 2176 + 1024 + 32;

    const bool isST = (m < 16);
    const float* w1 = isST ? st_w1 : ts_w1;
    const float* b1 = isST ? st_b1 : ts_b1;
    const float* w2 = isST ? st_w2 : ts_w2;
    const float* b2 = isST ? st_b2 : ts_b2;
    const float* asrc;
    const float* bsrc;
    int gi0, gj0;
    if (isST) {
        asrc = spatial + ((size_t)b * 1024 + m * 64) * 32;
        bsrc = temporal + (size_t)b * 64 * 32;
        gi0 = m * 64;
        gj0 = 1024;
    } else {
        asrc = temporal + (size_t)b * 64 * 32;
        bsrc = spatial + ((size_t)b * 1024 + (m - 16) * 64) * 32;
        gi0 = 1024;
        gj0 = (m - 16) * 64;
    }

    if (tid < 32) swh[tid] = __float2half2_rn(0.5f * w2[tid]);
    proj_pass_h2(asrc, w1, b1, Xt, Wo, ah, 0, tid);  // a' (sync covers swh)
    if (tid == 0) {
        float c = b2[0];
#pragma unroll
        for (int k = 0; k < 32; k++) c += 0.5f * w2[k];
        *c0p = c;
    }
    proj_pass_h2(bsrc, w1 + 1024, nullptr, Xt, Wo, bh, 1, tid);  // b'

    const int tx = tid & 15;  // col pairs tx*2, tx*2+1 -> cols tx*4..+3
    const int ty = tid >> 4;  // rows ty*4..+3
    __half2 acc2[4][2];
    const __half2 hz = __float2half2_rn(0.f);
#pragma unroll
    for (int i = 0; i < 4; i++) {
        acc2[i][0] = hz;
        acc2[i][1] = hz;
    }

    const __half2* ap = ah + ty * 4;
    const __half2* bp = (const __half2*)bh + tx * 2;
#pragma unroll
    for (int k = 0; k < 32; k++) {
        const uint2 aLo = *(const uint2*)(ap + k * 68);
        const uint2 aHi = *(const uint2*)(ap + k * 68 + 2);
        const uint2 bb = *(const uint2*)(bp + k * 36);
        const __half2 w2k = swh[k];
        const unsigned au[4] = {aLo.x, aLo.y, aHi.x, aHi.y};
#pragma unroll
        for (int i = 0; i < 4; i++) {
            const __half2 ai = u2h2(au[i]);
            const __half2 t0 = u2h2(tanh2_fast(h22u(__hadd2(ai, u2h2(bb.x)))));
            const __half2 t1 = u2h2(tanh2_fast(h22u(__hadd2(ai, u2h2(bb.y)))));
            acc2[i][0] = __hfma2(t0, w2k, acc2[i][0]);
            acc2[i][1] = __hfma2(t1, w2k, acc2[i][1]);
        }
    }

    const float c0 = *c0p;
    float* ob = out + ((size_t)b * 1088 + gi0 + ty * 4) * 1088 + gj0 + tx * 4;
#pragma unroll
    for (int i = 0; i < 4; i++) {
        const float2 f0 = __half22float2(acc2[i][0]);
        const float2 f1 = __half22float2(acc2[i][1]);
        float4 v;
        v.x = tanh_fast(fmaxf(f0.x + c0, 0.f));
        v.y = tanh_fast(fmaxf(f0.y + c0, 0.f));
        v.z = tanh_fast(fmaxf(f1.x + c0, 0.f));
        v.w = tanh_fast(fmaxf(f1.y + c0, 0.f));
        *(float4*)(ob + (size_t)i * 1088) = v;
    }
}

extern "C" void kernel_launch(void* const* d_in, const int* in_sizes, int n_in,
                              void* d_out, int out_size) {
    const float* spatial = (const float*)d_in[0];   // [32,1024,32]
    const float* temporal = (const float*)d_in[1];  // [32,64,32]
    const float* st_w1 = (const float*)d_in[2];     // [64,32]
    const float* st_b1 = (const float*)d_in[3];     // [32]
    const float* st_w2 = (const float*)d_in[4];     // [32,1]
    const float* st_b2 = (const float*)d_in[5];     // [1]
    const float* ts_w1 = (const float*)d_in[6];
    const float* ts_b1 = (const float*)d_in[7];
    const float* ts_w2 = (const float*)d_in[8];
    const float* ts_b2 = (const float*)d_in[9];
    float* out = (float*)d_out;                     // [32,1088,1088]

    adj_fused_kernel<<<32 * 108, 256>>>(spatial, temporal, st_w1, st_b1, st_w2,
                                        st_b2, ts_w1, ts_b1, ts_w2, ts_b2, out);
}